// round 11
// baseline (speedup 1.0000x reference)
#include <cuda_runtime.h>
#include <cuda_fp16.h>
#include <math.h>

// Problem constants (fixed by setup_inputs)
#define LMAXC 180
#define LC    181           // L = lmax+1
#define MMC   361           // 2*lmax+1
#define FC    50            // n_freqs
#define MT    64            // m-tile per CTA
#define KC    32            // k per chunk (16 packed u32 k-pairs)
#define AST   20            // A smem stride (u32) - conflict-free
#define BST   104           // B smem stride (u32) - conflict-free
#define NTHREADS 256
#define SIDEREALF 6.3003880989848976f
#define SQRT4PI   3.5449077018110318f

// Scratch (static device arrays; no runtime allocation)
__device__ float2 g_S2[MMC * FC];   // accumulator, f-contiguous complex
__device__ float  g_norm[FC];
__device__ float2 g_pg2[MMC];       // (cos, sin)(m*gamma)
__device__ float2 g_pa2[MMC];       // (cos, sin)(m*alpha)

__global__ void init_kernel(const float* __restrict__ euler) {
    int i = blockIdx.x * blockDim.x + threadIdx.x;
    if (i < MMC * FC) g_S2[i] = make_float2(0.f, 0.f);
    if (i < MMC) {
        float mf = (float)(i - LMAXC);
        float s, c;
        sincosf(mf * euler[2], &s, &c); g_pg2[i] = make_float2(c, s);
        sincosf(mf * euler[0], &s, &c); g_pa2[i] = make_float2(c, s);
    }
}

__device__ __forceinline__ unsigned packh2(__half a, __half b) {
    return ((unsigned)__half_as_ushort(b) << 16) | (unsigned)__half_as_ushort(a);
}

__device__ __forceinline__ void mma_f16(float* c,
    unsigned a0, unsigned a1, unsigned a2, unsigned a3,
    unsigned b0, unsigned b1)
{
    asm volatile(
        "mma.sync.aligned.m16n8k16.row.col.f32.f16.f16.f32 "
        "{%0,%1,%2,%3}, {%4,%5,%6,%7}, {%8,%9}, {%0,%1,%2,%3};"
        : "+f"(c[0]), "+f"(c[1]), "+f"(c[2]), "+f"(c[3])
        : "r"(a0), "r"(a1), "r"(a2), "r"(a3), "r"(b0), "r"(b1));
}

// ---- pipelined staging: ld (pure LDG -> regs), st (convert + STS) ----
struct Pre {
    float a0[4], a1[4];          // A: dl values (2 per iter)
    float b[4][4];               // B: br0, bi0, br1, bi1 per iter
};

__device__ __forceinline__ void ld_chunk(Pre& p,
    const float* __restrict__ dl_g,
    const float* __restrict__ br_g, const float* __restrict__ bi_g,
    int l, int jm0, int j1, int k0, int tid)
{
    #pragma unroll
    for (int it = 0; it < 4; it++) {
        int i = tid + it * NTHREADS;
        int pc = i & 15, rr = i >> 4;
        int jj = min(jm0 + rr, j1);
        const float* row = dl_g + ((size_t)l * MMC + jj) * MMC;
        int n0 = k0 + 2 * pc;
        p.a0[it] = row[min(n0,     2 * LMAXC)];
        p.a1[it] = row[min(n0 + 1, 2 * LMAXC)];
    }
    #pragma unroll
    for (int it = 0; it < 4; it++) {
        int i = tid + it * NTHREADS;
        float v0 = 0.f, v1 = 0.f, v2 = 0.f, v3 = 0.f;
        if (i < 16 * 52) {
            int kp = i & 15, f = i >> 4;
            int n0 = k0 + 2 * kp;
            if (f < FC) {
                size_t off = ((size_t)f * LC + l) * MMC;
                if (n0     <= j1) { v0 = br_g[off + n0];     v1 = bi_g[off + n0];     }
                if (n0 + 1 <= j1) { v2 = br_g[off + n0 + 1]; v3 = bi_g[off + n0 + 1]; }
            }
        }
        p.b[it][0] = v0; p.b[it][1] = v1; p.b[it][2] = v2; p.b[it][3] = v3;
    }
}

__device__ __forceinline__ void st_chunk(const Pre& p,
    unsigned (*ah)[AST], unsigned (*bh)[BST], unsigned (*bl)[BST],
    int k0, int tid)
{
    #pragma unroll
    for (int it = 0; it < 4; it++) {
        int i = tid + it * NTHREADS;
        int pc = i & 15, rr = i >> 4;
        ah[rr][pc] = packh2(__float2half_rn(p.a0[it]), __float2half_rn(p.a1[it]));
    }
    #pragma unroll
    for (int it = 0; it < 4; it++) {
        int i = tid + it * NTHREADS;
        if (i < 16 * 52) {
            int kp = i & 15, f = i >> 4;
            int n0 = k0 + 2 * kp;
            float2 p0 = g_pg2[min(n0,     2 * LMAXC)];
            float2 p1 = g_pg2[min(n0 + 1, 2 * LMAXC)];
            float br0 = p.b[it][0], bi0 = p.b[it][1];
            float br1 = p.b[it][2], bi1 = p.b[it][3];
            float re0 = br0 * p0.x + bi0 * p0.y, im0 = br0 * p0.y - bi0 * p0.x;
            float re1 = br1 * p1.x + bi1 * p1.y, im1 = br1 * p1.y - bi1 * p1.x;
            __half rh0 = __float2half_rn(re0), rh1 = __float2half_rn(re1);
            __half ih0 = __float2half_rn(im0), ih1 = __float2half_rn(im1);
            __half rl0 = __float2half_rn(re0 - __half2float(rh0));
            __half rl1 = __float2half_rn(re1 - __half2float(rh1));
            __half il0 = __float2half_rn(im0 - __half2float(ih0));
            __half il1 = __float2half_rn(im1 - __half2float(ih1));
            int col = 2 * f;                   // f=50,51 -> pad cols 100..103 (zeros)
            bh[kp][col]     = packh2(rh0, rh1);
            bl[kp][col]     = packh2(rl0, rl1);
            bh[kp][col + 1] = packh2(ih0, ih1);
            bl[kp][col + 1] = packh2(il0, il1);
        }
    }
}

// Per (m-tile, l) CTA: fp16 2-term split tensor-core banded GEMM
//   D[m, 2f] = sum_n dl[l,m,n] * conj(beam[f,l,n] * pg[n])
// epilogue: S[m,f] += conj(pa[m]) * D[m,f] * sky[f,l,m]; l==0 writes norm.
__global__ void __launch_bounds__(NTHREADS, 2) conv_kernel(
    const float* __restrict__ br_g, const float* __restrict__ bi_g,
    const float* __restrict__ sr_g, const float* __restrict__ si_g,
    const float* __restrict__ dl_g)
{
    const int l  = (LC - 1) - blockIdx.y;       // heavy CTAs first
    const int j0 = LMAXC - l, j1 = LMAXC + l;
    const int ntiles_m = (2 * l + 1 + MT - 1) / MT;
    const int mt = blockIdx.x;
    if (mt >= ntiles_m) return;
    const int jm0 = j0 + mt * MT;

    __shared__ unsigned Ah[2][MT][AST];          // 10240 B
    __shared__ unsigned Bh[2][16][BST];          // 13312 B
    __shared__ unsigned Bl[2][16][BST];          // 13312 B

    const int tid   = threadIdx.x;
    const int lane  = tid & 31;
    const int warp  = tid >> 5;
    const int mhalf = warp & 1;                  // 0/1: m-rows [0,32) / [32,64)
    const int ngrp  = warp >> 1;                 // 0..3 n-groups
    const int tbase = (ngrp == 0) ? 0 : 4 + 3 * (ngrp - 1);   // 0,4,7,10
    const int tcnt  = (ngrp == 0) ? 4 : 3;
    const int g  = lane >> 2;
    const int t4 = lane & 3;

    float acc[2][4][4];
    #pragma unroll
    for (int a = 0; a < 2; a++)
        #pragma unroll
        for (int t = 0; t < 4; t++)
            #pragma unroll
            for (int q = 0; q < 4; q++) acc[a][t][q] = 0.0f;

    const int nch = (2 * l + 1 + KC - 1) / KC;

    Pre pre;
    ld_chunk(pre, dl_g, br_g, bi_g, l, jm0, j1, j0, tid);
    st_chunk(pre, Ah[0], Bh[0], Bl[0], j0, tid);
    __syncthreads();

    for (int c = 0; c < nch; c++) {
        const int k0n = j0 + (c + 1) * KC;
        const bool more = (c + 1 < nch);
        if (more)
            ld_chunk(pre, dl_g, br_g, bi_g, l, jm0, j1, k0n, tid);  // LDGs in flight

        // ---- MMA on current buffer (overlaps prefetch latency) ----
        {
            const unsigned (*ah)[AST] = Ah[c & 1];
            const unsigned (*bhp)[BST] = Bh[c & 1];
            const unsigned (*blp)[BST] = Bl[c & 1];
            const int k0 = j0 + c * KC;
            const int nks = (j1 - k0 + 1 > 16) ? 2 : 1;
            #pragma unroll
            for (int ks = 0; ks < 2; ks++) {
                if (ks < nks) {
                    const int ac = ks * 8 + t4;
                    const int ar0 = mhalf * 32 + g;
                    unsigned a00 = ah[ar0][ac],      a01 = ah[ar0 + 8][ac];
                    unsigned a02 = ah[ar0][ac + 4],  a03 = ah[ar0 + 8][ac + 4];
                    unsigned a10 = ah[ar0 + 16][ac],     a11 = ah[ar0 + 24][ac];
                    unsigned a12 = ah[ar0 + 16][ac + 4], a13 = ah[ar0 + 24][ac + 4];
                    const int bk = ks * 8 + t4;
                    #pragma unroll
                    for (int t = 0; t < 4; t++) {
                        if (t < tcnt) {
                            int n0 = (tbase + t) * 8;
                            unsigned b0h = bhp[bk][n0 + g], b1h = bhp[bk + 4][n0 + g];
                            unsigned b0l = blp[bk][n0 + g], b1l = blp[bk + 4][n0 + g];
                            mma_f16(acc[0][t], a00, a01, a02, a03, b0h, b1h);
                            mma_f16(acc[0][t], a00, a01, a02, a03, b0l, b1l);
                            mma_f16(acc[1][t], a10, a11, a12, a13, b0h, b1h);
                            mma_f16(acc[1][t], a10, a11, a12, a13, b0l, b1l);
                        }
                    }
                }
            }
        }

        if (more)
            st_chunk(pre, Ah[(c + 1) & 1], Bh[(c + 1) & 1], Bl[(c + 1) & 1], k0n, tid);
        __syncthreads();
    }

    // ---- epilogue: S[m,f] += conj(pa[m]) * D * sky ----
    #pragma unroll
    for (int mf = 0; mf < 2; mf++) {
        const int r0 = jm0 + mhalf * 32 + mf * 16 + g;
        const int r1 = r0 + 8;
        float2 pa0 = g_pa2[min(r0, 2 * LMAXC)];
        float2 pa1 = g_pa2[min(r1, 2 * LMAXC)];
        const bool v0 = (r0 <= j1);
        const bool v1 = (r1 <= j1);
        #pragma unroll
        for (int t = 0; t < 4; t++) {
            if (t < tcnt) {
                int f = 4 * (tbase + t) + t4;
                if (f < FC) {
                    if (v0) {
                        float dre = acc[mf][t][0], dim = acc[mf][t][1];
                        float z1r = pa0.x * dre - pa0.y * dim;
                        float z1i = pa0.x * dim + pa0.y * dre;
                        size_t soff = ((size_t)f * LC + l) * MMC + r0;
                        float skr = sr_g[soff], ski = si_g[soff];
                        atomicAdd(&g_S2[r0 * FC + f].x, z1r * skr - z1i * ski);
                        atomicAdd(&g_S2[r0 * FC + f].y, z1r * ski + z1i * skr);
                    }
                    if (v1) {
                        float dre = acc[mf][t][2], dim = acc[mf][t][3];
                        float z1r = pa1.x * dre - pa1.y * dim;
                        float z1i = pa1.x * dim + pa1.y * dre;
                        size_t soff = ((size_t)f * LC + l) * MMC + r1;
                        float skr = sr_g[soff], ski = si_g[soff];
                        atomicAdd(&g_S2[r1 * FC + f].x, z1r * skr - z1i * ski);
                        atomicAdd(&g_S2[r1 * FC + f].y, z1r * ski + z1i * skr);
                    }
                    if (l == 0 && mhalf == 0 && mf == 0 && g == 0) {
                        // r0 == LMAXC, pa = 1: norm = sqrt(4pi) * Re(D)
                        g_norm[f] = SQRT4PI * acc[0][t][0];
                    }
                }
            }
        }
    }
}

// Per-time block, 1024 threads = 16 m-chunks x 64 f-slots.
#define VNT 1024
#define VCH 16
#define VMS 23      // ceil(361/16)
__global__ void __launch_bounds__(VNT) vis_kernel(
    const float* __restrict__ times,
    const float* __restrict__ fsky,
    const float* __restrict__ tg,
    float* __restrict__ out)
{
    const int t = blockIdx.x;
    __shared__ float phc[MMC], phs[MMC];
    __shared__ float part[VNT];

    const float phi = SIDEREALF * times[t];
    if (threadIdx.x < MMC) {
        float s, c;
        sincosf((float)((int)threadIdx.x - LMAXC) * phi, &s, &c);
        phc[threadIdx.x] = c; phs[threadIdx.x] = s;
    }
    __syncthreads();

    const int f  = threadIdx.x & 63;      // 0..63, active f < FC
    const int ch = threadIdx.x >> 6;      // 0..15
    const int m0 = ch * VMS;
    const int m1 = min(m0 + VMS, MMC);

    float acc = 0.0f;
    if (f < FC) {
        int m = m0;
        for (; m + 4 <= m1; m += 4) {     // 4 independent LDGs issued together
            float2 s0 = g_S2[(m    ) * FC + f];
            float2 s1 = g_S2[(m + 1) * FC + f];
            float2 s2 = g_S2[(m + 2) * FC + f];
            float2 s3 = g_S2[(m + 3) * FC + f];
            acc += phc[m]     * s0.x - phs[m]     * s0.y;
            acc += phc[m + 1] * s1.x - phs[m + 1] * s1.y;
            acc += phc[m + 2] * s2.x - phs[m + 2] * s2.y;
            acc += phc[m + 3] * s3.x - phs[m + 3] * s3.y;
        }
        for (; m < m1; m++) {
            float2 sv = g_S2[m * FC + f];
            acc += phc[m] * sv.x - phs[m] * sv.y;
        }
    }
    part[threadIdx.x] = acc;
    __syncthreads();

    if (ch == 0 && f < FC) {
        float tot = part[f];
        #pragma unroll
        for (int c = 1; c < VCH; c++) tot += part[f + 64 * c];
        float v  = tot / g_norm[f];
        float fs = fsky[f];
        out[t * FC + f] = fs * v + (1.0f - fs) * 300.0f * tg[0];
    }
}

extern "C" void kernel_launch(void* const* d_in, const int* in_sizes, int n_in,
                              void* d_out, int out_size)
{
    const float* br    = (const float*)d_in[0];
    const float* bi    = (const float*)d_in[1];
    const float* sr    = (const float*)d_in[2];
    const float* si    = (const float*)d_in[3];
    const float* dl    = (const float*)d_in[4];
    const float* euler = (const float*)d_in[5];
    const float* times = (const float*)d_in[6];
    const float* fsky  = (const float*)d_in[7];
    const float* tg    = (const float*)d_in[8];
    float* out = (float*)d_out;
    const int T = in_sizes[6];

    init_kernel<<<(MMC * FC + 255) / 256, 256>>>(euler);

    dim3 grid((MMC + MT - 1) / MT, LC);
    conv_kernel<<<grid, NTHREADS>>>(br, bi, sr, si, dl);

    vis_kernel<<<T, VNT>>>(times, fsky, tg, out);
}

// round 12
// speedup vs baseline: 1.2262x; 1.2262x over previous
#include <cuda_runtime.h>
#include <cuda_fp16.h>
#include <math.h>

// Problem constants (fixed by setup_inputs)
#define LMAXC 180
#define LC    181           // L = lmax+1
#define MMC   361           // 2*lmax+1
#define FC    50            // n_freqs
#define MT    64            // m-tile per CTA
#define KC    32            // k per chunk (16 packed u32 k-pairs)
#define AST   20            // A smem stride (u32) - conflict-free
#define BST   104           // B smem stride (u32) - conflict-free
#define NTHREADS 256
#define SIDEREALF 6.3003880989848976f
#define SQRT4PI   3.5449077018110318f

// Scratch (static device arrays; no runtime allocation)
__device__ float2 g_S2[MMC * FC];   // accumulator, f-contiguous complex
__device__ float  g_norm[FC];
__device__ float2 g_pg2[MMC];       // (cos, sin)(m*gamma)
__device__ float2 g_pa2[MMC];       // (cos, sin)(m*alpha)

__global__ void init_kernel(const float* __restrict__ euler) {
    int i = blockIdx.x * blockDim.x + threadIdx.x;
    if (i < MMC * FC) g_S2[i] = make_float2(0.f, 0.f);
    if (i < MMC) {
        float mf = (float)(i - LMAXC);
        float s, c;
        sincosf(mf * euler[2], &s, &c); g_pg2[i] = make_float2(c, s);
        sincosf(mf * euler[0], &s, &c); g_pa2[i] = make_float2(c, s);
    }
}

__device__ __forceinline__ unsigned packh2(__half a, __half b) {
    return ((unsigned)__half_as_ushort(b) << 16) | (unsigned)__half_as_ushort(a);
}

__device__ __forceinline__ void mma_f16(float* c,
    unsigned a0, unsigned a1, unsigned a2, unsigned a3,
    unsigned b0, unsigned b1)
{
    asm volatile(
        "mma.sync.aligned.m16n8k16.row.col.f32.f16.f16.f32 "
        "{%0,%1,%2,%3}, {%4,%5,%6,%7}, {%8,%9}, {%0,%1,%2,%3};"
        : "+f"(c[0]), "+f"(c[1]), "+f"(c[2]), "+f"(c[3])
        : "r"(a0), "r"(a1), "r"(a2), "r"(a3), "r"(b0), "r"(b1));
}

// Stage one k-chunk into smem (A: fp16; B: fp16 — no split tiles)
__device__ __forceinline__ void stage_chunk(
    unsigned (*ah)[AST], unsigned (*bh)[BST],
    const float* __restrict__ dl_g,
    const float* __restrict__ br_g, const float* __restrict__ bi_g,
    int l, int jm0, int j1, int k0, int tid)
{
    // ---- A: dl rows jm0..jm0+63, 16 packed k-pairs ----
    #pragma unroll
    for (int it = 0; it < 4; it++) {
        int i = tid + it * NTHREADS;           // 1024 total
        int pc = i & 15, rr = i >> 4;
        int jj = min(jm0 + rr, j1);            // rows past band: clamped (masked later)
        const float* row = dl_g + ((size_t)l * MMC + jj) * MMC;
        int n0 = k0 + 2 * pc;
        float v0 = row[min(n0,     2 * LMAXC)];  // cols past band: garbage x B(=0)
        float v1 = row[min(n0 + 1, 2 * LMAXC)];
        ah[rr][pc] = packh2(__float2half_rn(v0), __float2half_rn(v1));
    }
    // ---- B: conj(beam*pg), re/im columns ----
    #pragma unroll
    for (int it = 0; it < 4; it++) {
        int i = tid + it * NTHREADS;           // 832 total
        if (i < 16 * 52) {
            int kp = i & 15, f = i >> 4;
            int n0 = k0 + 2 * kp;
            float br0 = 0.f, bi0 = 0.f, br1 = 0.f, bi1 = 0.f;
            if (f < FC) {
                size_t off = ((size_t)f * LC + l) * MMC;
                if (n0     <= j1) { br0 = br_g[off + n0];     bi0 = bi_g[off + n0];     }
                if (n0 + 1 <= j1) { br1 = br_g[off + n0 + 1]; bi1 = bi_g[off + n0 + 1]; }
            }
            float2 p0 = g_pg2[min(n0,     2 * LMAXC)];
            float2 p1 = g_pg2[min(n0 + 1, 2 * LMAXC)];
            float re0 = br0 * p0.x + bi0 * p0.y, im0 = br0 * p0.y - bi0 * p0.x;
            float re1 = br1 * p1.x + bi1 * p1.y, im1 = br1 * p1.y - bi1 * p1.x;
            int col = 2 * f;                   // f=50,51 -> pad cols 100..103 (zeros)
            bh[kp][col]     = packh2(__float2half_rn(re0), __float2half_rn(re1));
            bh[kp][col + 1] = packh2(__float2half_rn(im0), __float2half_rn(im1));
        }
    }
}

// Per (m-tile, l) CTA: pure-fp16 tensor-core banded GEMM
//   D[m, 2f] = sum_n dl[l,m,n] * conj(beam[f,l,n] * pg[n])
// epilogue: S[m,f] += conj(pa[m]) * D[m,f] * sky[f,l,m]; l==0 writes norm.
__global__ void __launch_bounds__(NTHREADS) conv_kernel(
    const float* __restrict__ br_g, const float* __restrict__ bi_g,
    const float* __restrict__ sr_g, const float* __restrict__ si_g,
    const float* __restrict__ dl_g)
{
    const int l  = (LC - 1) - blockIdx.y;       // heavy CTAs first
    const int j0 = LMAXC - l, j1 = LMAXC + l;
    const int ntiles_m = (2 * l + 1 + MT - 1) / MT;
    const int mt = blockIdx.x;
    if (mt >= ntiles_m) return;
    const int jm0 = j0 + mt * MT;

    __shared__ unsigned Ah[2][MT][AST];          // 10240 B
    __shared__ unsigned Bh[2][16][BST];          // 13312 B

    const int tid   = threadIdx.x;
    const int lane  = tid & 31;
    const int warp  = tid >> 5;
    const int mhalf = warp & 1;                  // 0/1: m-rows [0,32) / [32,64)
    const int ngrp  = warp >> 1;                 // 0..3 n-groups
    const int tbase = (ngrp == 0) ? 0 : 4 + 3 * (ngrp - 1);   // 0,4,7,10
    const int tcnt  = (ngrp == 0) ? 4 : 3;
    const int g  = lane >> 2;
    const int t4 = lane & 3;

    float acc[2][4][4];
    #pragma unroll
    for (int a = 0; a < 2; a++)
        #pragma unroll
        for (int t = 0; t < 4; t++)
            #pragma unroll
            for (int q = 0; q < 4; q++) acc[a][t][q] = 0.0f;

    const int nch = (2 * l + 1 + KC - 1) / KC;

    stage_chunk(Ah[0], Bh[0], dl_g, br_g, bi_g, l, jm0, j1, j0, tid);
    __syncthreads();

    for (int c = 0; c < nch; c++) {
        if (c + 1 < nch)
            stage_chunk(Ah[(c + 1) & 1], Bh[(c + 1) & 1],
                        dl_g, br_g, bi_g, l, jm0, j1, j0 + (c + 1) * KC, tid);

        const unsigned (*ah)[AST] = Ah[c & 1];
        const unsigned (*bhp)[BST] = Bh[c & 1];
        const int k0 = j0 + c * KC;
        const int nks = (j1 - k0 + 1 > 16) ? 2 : 1;

        #pragma unroll
        for (int ks = 0; ks < 2; ks++) {
            if (ks < nks) {
                const int ac = ks * 8 + t4;
                const int ar0 = mhalf * 32 + g;
                unsigned a00 = ah[ar0][ac],      a01 = ah[ar0 + 8][ac];
                unsigned a02 = ah[ar0][ac + 4],  a03 = ah[ar0 + 8][ac + 4];
                unsigned a10 = ah[ar0 + 16][ac],     a11 = ah[ar0 + 24][ac];
                unsigned a12 = ah[ar0 + 16][ac + 4], a13 = ah[ar0 + 24][ac + 4];
                const int bk = ks * 8 + t4;
                #pragma unroll
                for (int t = 0; t < 4; t++) {
                    if (t < tcnt) {
                        int n0 = (tbase + t) * 8;
                        unsigned b0 = bhp[bk][n0 + g], b1 = bhp[bk + 4][n0 + g];
                        mma_f16(acc[0][t], a00, a01, a02, a03, b0, b1);
                        mma_f16(acc[1][t], a10, a11, a12, a13, b0, b1);
                    }
                }
            }
        }
        __syncthreads();   // protect smem before next chunk's writes
    }

    // ---- epilogue: S[m,f] += conj(pa[m]) * D * sky ----
    #pragma unroll
    for (int mf = 0; mf < 2; mf++) {
        const int r0 = jm0 + mhalf * 32 + mf * 16 + g;
        const int r1 = r0 + 8;
        float2 pa0 = g_pa2[min(r0, 2 * LMAXC)];
        float2 pa1 = g_pa2[min(r1, 2 * LMAXC)];
        const bool v0 = (r0 <= j1);
        const bool v1 = (r1 <= j1);
        #pragma unroll
        for (int t = 0; t < 4; t++) {
            if (t < tcnt) {
                int f = 4 * (tbase + t) + t4;
                if (f < FC) {
                    if (v0) {
                        float dre = acc[mf][t][0], dim = acc[mf][t][1];
                        float z1r = pa0.x * dre - pa0.y * dim;
                        float z1i = pa0.x * dim + pa0.y * dre;
                        size_t soff = ((size_t)f * LC + l) * MMC + r0;
                        float skr = sr_g[soff], ski = si_g[soff];
                        atomicAdd(&g_S2[r0 * FC + f].x, z1r * skr - z1i * ski);
                        atomicAdd(&g_S2[r0 * FC + f].y, z1r * ski + z1i * skr);
                    }
                    if (v1) {
                        float dre = acc[mf][t][2], dim = acc[mf][t][3];
                        float z1r = pa1.x * dre - pa1.y * dim;
                        float z1i = pa1.x * dim + pa1.y * dre;
                        size_t soff = ((size_t)f * LC + l) * MMC + r1;
                        float skr = sr_g[soff], ski = si_g[soff];
                        atomicAdd(&g_S2[r1 * FC + f].x, z1r * skr - z1i * ski);
                        atomicAdd(&g_S2[r1 * FC + f].y, z1r * ski + z1i * skr);
                    }
                    if (l == 0 && mhalf == 0 && mf == 0 && g == 0) {
                        // r0 == LMAXC, pa = 1: norm = sqrt(4pi) * Re(D)
                        g_norm[f] = SQRT4PI * acc[0][t][0];
                    }
                }
            }
        }
    }
}

// Per-time block, 1024 threads = 16 m-chunks x 64 f-slots.
#define VNT 1024
#define VCH 16
#define VMS 23      // ceil(361/16)
__global__ void __launch_bounds__(VNT) vis_kernel(
    const float* __restrict__ times,
    const float* __restrict__ fsky,
    const float* __restrict__ tg,
    float* __restrict__ out)
{
    const int t = blockIdx.x;
    __shared__ float phc[MMC], phs[MMC];
    __shared__ float part[VNT];

    const float phi = SIDEREALF * times[t];
    if (threadIdx.x < MMC) {
        float s, c;
        sincosf((float)((int)threadIdx.x - LMAXC) * phi, &s, &c);
        phc[threadIdx.x] = c; phs[threadIdx.x] = s;
    }
    __syncthreads();

    const int f  = threadIdx.x & 63;      // 0..63, active f < FC
    const int ch = threadIdx.x >> 6;      // 0..15
    const int m0 = ch * VMS;
    const int m1 = min(m0 + VMS, MMC);

    float acc = 0.0f;
    if (f < FC) {
        int m = m0;
        for (; m + 4 <= m1; m += 4) {     // 4 independent LDGs issued together
            float2 s0 = g_S2[(m    ) * FC + f];
            float2 s1 = g_S2[(m + 1) * FC + f];
            float2 s2 = g_S2[(m + 2) * FC + f];
            float2 s3 = g_S2[(m + 3) * FC + f];
            acc += phc[m]     * s0.x - phs[m]     * s0.y;
            acc += phc[m + 1] * s1.x - phs[m + 1] * s1.y;
            acc += phc[m + 2] * s2.x - phs[m + 2] * s2.y;
            acc += phc[m + 3] * s3.x - phs[m + 3] * s3.y;
        }
        for (; m < m1; m++) {
            float2 sv = g_S2[m * FC + f];
            acc += phc[m] * sv.x - phs[m] * sv.y;
        }
    }
    part[threadIdx.x] = acc;
    __syncthreads();

    if (ch == 0 && f < FC) {
        float tot = part[f];
        #pragma unroll
        for (int c = 1; c < VCH; c++) tot += part[f + 64 * c];
        float v  = tot / g_norm[f];
        float fs = fsky[f];
        out[t * FC + f] = fs * v + (1.0f - fs) * 300.0f * tg[0];
    }
}

extern "C" void kernel_launch(void* const* d_in, const int* in_sizes, int n_in,
                              void* d_out, int out_size)
{
    const float* br    = (const float*)d_in[0];
    const float* bi    = (const float*)d_in[1];
    const float* sr    = (const float*)d_in[2];
    const float* si    = (const float*)d_in[3];
    const float* dl    = (const float*)d_in[4];
    const float* euler = (const float*)d_in[5];
    const float* times = (const float*)d_in[6];
    const float* fsky  = (const float*)d_in[7];
    const float* tg    = (const float*)d_in[8];
    float* out = (float*)d_out;
    const int T = in_sizes[6];

    init_kernel<<<(MMC * FC + 255) / 256, 256>>>(euler);

    dim3 grid((MMC + MT - 1) / MT, LC);
    conv_kernel<<<grid, NTHREADS>>>(br, bi, sr, si, dl);

    vis_kernel<<<T, VNT>>>(times, fsky, tg, out);
}